// round 10
// baseline (speedup 1.0000x reference)
#include <cuda_runtime.h>

#define NPG   111
#define PADJ  112                 // padded M row width (28 quads)
#define HDIM  32
#define HDW   64                  // hdup row: 32 (h,h) pairs = 16 16B units
#define EPG   (NPG*(NPG-1))       // 12210
#define NWARP 28
#define NTHR  (NWARP*32)          // 896
#define BGRAPHS 128

typedef unsigned long long ull;
#define FMA2(d,a,b,c) asm("fma.rn.f32x2 %0, %1, %2, %3;" : "=l"(d) : "l"(a), "l"(b), "l"(c))
#define ADD2(d,a,b)   asm("add.rn.f32x2 %0, %1, %2;" : "=l"(d) : "l"(a), "l"(b))
#define PACK2(d,lo,hi) asm("mov.b64 %0, {%1, %2};" : "=l"(d) : "f"(lo), "f"(hi))
#define UNPACK2(lo,hi,s) asm("mov.b64 {%0, %1}, %2;" : "=f"(lo), "=f"(hi) : "l"(s))

// Unit swizzle on 16B units of a 256B row: u in [0,16) -> u ^ (u>>3). Bijective,
// in-row; makes the 8 per-chunk unit streams hit 8 distinct bank groups.
__device__ __forceinline__ int uswz(int u) { return (u ^ (u >> 3)) * 4; }  // float offset

struct __align__(16) Smem {
  float Mpre[3][NPG*PADJ];          // 149184 B pre-collapsed ea.c_l; exp in place
  float feat[NPG*HDIM];             // 14208 B
  alignas(16) float hdup[NPG*HDW];  // 28416 B h duplicated (h,h), unit-swizzled
  alignas(16) ull   pbuf[2*1792];   // 28672 B bufA(+scratch overlay) + bufB
  alignas(16) float invbuf[PADJ];
  alignas(16) float hs[PADJ];
  alignas(16) float hd[PADJ];       // hd[111]=0 pad
  alignas(16) float xs[PADJ];
  float asv[3][HDIM], adv[3][HDIM], bsh[3][HDIM];
  float w0[HDIM];
  float2 cvec[3];
  float l0s[2];
};

__device__ __forceinline__ void run_layer(Smem& S, int warp, int lane, int tid,
                                          int layer, bool relu_out,
                                          const float* __restrict__ Wg)
{
  // ---- (a) h rows 4w..4w+3 -> hdup (dup + unit swizzle); fused hs/hd ----
  {
    // writer: lane k -> chunk kch=k>>2, pair rr=k&3; unit u=2kch+(rr>>1), slot rr&1
    const int kch = lane >> 2, rr = lane & 3;
    const int woff = uswz(2*kch + (rr >> 1)) + (rr & 1)*2;
    if (layer == 0) {
      const float wl = S.w0[lane], ds = S.l0s[0], dd = S.l0s[1];
#pragma unroll
      for (int r = 0; r < 4; ++r) {
        const int i = 4*warp + r;
        if (i < NPG) {
          const float xv = S.xs[i];
          const float hv = xv * wl;
          ull hp; PACK2(hp, hv, hv);
          *reinterpret_cast<ull*>(&S.hdup[i*HDW + woff]) = hp;
          if (lane == 0) { S.hs[i] = xv*ds; S.hd[i] = xv*dd; }
        }
      }
    } else {
      ull wp[16];                                  // W[:,lane] packed pairs (L2)
#pragma unroll
      for (int m2 = 0; m2 < 16; ++m2)
        PACK2(wp[m2], __ldg(&Wg[(2*m2)*HDIM + lane]), __ldg(&Wg[(2*m2+1)*HDIM + lane]));
#pragma unroll
      for (int r = 0; r < 4; ++r) {
        const int i = 4*warp + r;
        if (i < NPG) {
          const ulonglong2* f2 = reinterpret_cast<const ulonglong2*>(S.feat + i*HDIM);
          ull ae = 0ull, ao = 0ull;
#pragma unroll
          for (int m4 = 0; m4 < 8; ++m4) {
            const ulonglong2 f = f2[m4];           // LDS.128 broadcast
            FMA2(ae, f.x, wp[2*m4],   ae);
            FMA2(ao, f.y, wp[2*m4+1], ao);
          }
          float l0,h0,l1,h1; UNPACK2(l0,h0,ae); UNPACK2(l1,h1,ao);
          const float hv = (l0+l1) + (h0+h1);
          ull hp; PACK2(hp, hv, hv);
          *reinterpret_cast<ull*>(&S.hdup[i*HDW + woff]) = hp;
        }
      }
      __syncwarp();
      // hs/hd: lane=(r,kc); shfl is UNCONDITIONAL (all 32 lanes), loads clamped
      {
        const int r = lane >> 3, kc = lane & 7;
        const int row  = 4*warp + r;
        const int rowc = (row < NPG) ? row : NPG-1;
        const int s0o = uswz(2*kc), s1o = uswz(2*kc + 1);
        const float h0 = S.hdup[rowc*HDW + s0o],     h1 = S.hdup[rowc*HDW + s0o + 2];
        const float h2 = S.hdup[rowc*HDW + s1o],     h3 = S.hdup[rowc*HDW + s1o + 2];
        const float4 a4 = *reinterpret_cast<const float4*>(&S.asv[layer][4*kc]);
        const float4 d4 = *reinterpret_cast<const float4*>(&S.adv[layer][4*kc]);
        float ss = fmaf(h0,a4.x, fmaf(h1,a4.y, fmaf(h2,a4.z, h3*a4.w)));
        float sd = fmaf(h0,d4.x, fmaf(h1,d4.y, fmaf(h2,d4.z, h3*d4.w)));
#pragma unroll
        for (int o = 4; o; o >>= 1) {
          ss += __shfl_xor_sync(0xffffffffu, ss, o);
          sd += __shfl_xor_sync(0xffffffffu, sd, o);
        }
        if (kc == 0 && row < NPG) { S.hs[row] = ss; S.hd[row] = sd; }
      }
    }
  }
  __syncthreads();

  // ---- (b) Phase A: alpha -> exp in place; 14 part rows in pbuf overlay ----
  {
    float* M = S.Mpre[layer];
    float* part = reinterpret_cast<float*>(S.pbuf);
    const int dp = tid & 63, jc = tid >> 6;        // jc in [0,14)
    if (dp < 56) {
      const int d0 = 2*dp;
      const float hd0 = S.hd[d0], hd1 = S.hd[d0+1];
      const int j0 = jc*8;
      const int j1 = (j0 + 8 < NPG) ? j0 + 8 : NPG;
      float s0 = 0.f, s1 = 0.f;
#pragma unroll 2
      for (int j = j0; j < j1; ++j) {
        const float2 m = *reinterpret_cast<const float2*>(&M[j*PADJ + d0]);
        const float hsj = S.hs[j];                 // broadcast
        float a0 = m.x + hsj + hd0;
        float a1 = m.y + hsj + hd1;
        a0 = fmaxf(a0, 0.2f*a0);                   // leaky_relu
        a1 = fmaxf(a1, 0.2f*a1);
        const float e0 = __expf(a0), e1 = __expf(a1);
        *reinterpret_cast<float2*>(&M[j*PADJ + d0]) = make_float2(e0, e1);
        s0 += e0; s1 += e1;
      }
      *reinterpret_cast<float2*>(&part[jc*PADJ + d0]) = make_float2(s0, s1);
    }
  }
  __syncthreads();

  // ---- inverse softmax sums ----
  if (tid < PADJ) {
    const float* part = reinterpret_cast<const float*>(S.pbuf);
    float s = 0.f;
#pragma unroll
    for (int k = 0; k < 14; ++k) s += part[k*PADJ + tid];
    S.invbuf[tid] = 1.f / s;
  }
  __syncthreads();

  // ---- (c) Phase B: 7 groups x 4 j-quarters; 16d x 32k per warp ----
  {
    const int g = warp % 7, q = warp / 7;
    const int dq = lane >> 3, kc = lane & 7;
    const int Q = g*4 + dq;                        // dst quad in [0,28)
    const ulonglong2* Mv = reinterpret_cast<const ulonglong2*>(S.Mpre[layer]);
    const int hb0 = uswz(2*kc), hb1 = uswz(2*kc + 1);
    const int j0 = q*28, j1 = (q == 3) ? NPG : j0 + 28;
    ull A00=0,A01=0,A02=0,A03=0,A10=0,A11=0,A12=0,A13=0;
#pragma unroll 4
    for (int j = j0; j < j1; ++j) {
      const ulonglong2 m = Mv[j*28 + Q];           // 64B distinct/warp: 1 wf
      const ulonglong2 ha = *reinterpret_cast<const ulonglong2*>(&S.hdup[j*HDW + hb0]);
      const ulonglong2 hc = *reinterpret_cast<const ulonglong2*>(&S.hdup[j*HDW + hb1]);
      FMA2(A00, m.x, ha.x, A00); FMA2(A01, m.x, ha.y, A01);
      FMA2(A02, m.x, hc.x, A02); FMA2(A03, m.x, hc.y, A03);
      FMA2(A10, m.y, ha.x, A10); FMA2(A11, m.y, ha.y, A11);
      FMA2(A12, m.y, hc.x, A12); FMA2(A13, m.y, hc.y, A13);
    }
    ull* bufA = S.pbuf;
    ull* bufB = S.pbuf + 1792;
    const int base = Q*64 + kc*4;
    if (q == 1 || q == 3) {                        // stage A: quarters 1,3 dump
      ull* b = (q == 1) ? bufA : bufB;
      b[base+0]=A00; b[base+1]=A01; b[base+2]=A02; b[base+3]=A03;
      b[base+32]=A10; b[base+33]=A11; b[base+34]=A12; b[base+35]=A13;
    }
    __syncthreads();
    if (q == 0) {                                  // stage B: 0+=1 ; 2+=3 -> bufB
      ull t;
      t=bufA[base+0];  ADD2(A00,A00,t); t=bufA[base+1];  ADD2(A01,A01,t);
      t=bufA[base+2];  ADD2(A02,A02,t); t=bufA[base+3];  ADD2(A03,A03,t);
      t=bufA[base+32]; ADD2(A10,A10,t); t=bufA[base+33]; ADD2(A11,A11,t);
      t=bufA[base+34]; ADD2(A12,A12,t); t=bufA[base+35]; ADD2(A13,A13,t);
    } else if (q == 2) {
      ull t;
      t=bufB[base+0];  ADD2(A00,A00,t); t=bufB[base+1];  ADD2(A01,A01,t);
      t=bufB[base+2];  ADD2(A02,A02,t); t=bufB[base+3];  ADD2(A03,A03,t);
      t=bufB[base+32]; ADD2(A10,A10,t); t=bufB[base+33]; ADD2(A11,A11,t);
      t=bufB[base+34]; ADD2(A12,A12,t); t=bufB[base+35]; ADD2(A13,A13,t);
      bufB[base+0]=A00; bufB[base+1]=A01; bufB[base+2]=A02; bufB[base+3]=A03;
      bufB[base+32]=A10; bufB[base+33]=A11; bufB[base+34]=A12; bufB[base+35]=A13;
    }
    __syncthreads();
    if (q == 0) {                                  // stage C: final, scale, store
      ull t;
      t=bufB[base+0];  ADD2(A00,A00,t); t=bufB[base+1];  ADD2(A01,A01,t);
      t=bufB[base+2];  ADD2(A02,A02,t); t=bufB[base+3];  ADD2(A03,A03,t);
      t=bufB[base+32]; ADD2(A10,A10,t); t=bufB[base+33]; ADD2(A11,A11,t);
      t=bufB[base+34]; ADD2(A12,A12,t); t=bufB[base+35]; ADD2(A13,A13,t);
      const float4 iv = *reinterpret_cast<const float4*>(&S.invbuf[4*Q]);
      const float4 bb = *reinterpret_cast<const float4*>(&S.bsh[layer][4*kc]);
      float v0[4], v1[4], v2[4], v3[4];
      UNPACK2(v0[0], v1[0], A00); UNPACK2(v0[1], v1[1], A01);
      UNPACK2(v0[2], v1[2], A02); UNPACK2(v0[3], v1[3], A03);
      UNPACK2(v2[0], v3[0], A10); UNPACK2(v2[1], v3[1], A11);
      UNPACK2(v2[2], v3[2], A12); UNPACK2(v2[3], v3[3], A13);
      const float bv[4] = {bb.x, bb.y, bb.z, bb.w};
#pragma unroll
      for (int kk = 0; kk < 4; ++kk) {
        v0[kk] = fmaf(v0[kk], iv.x, bv[kk]);
        v1[kk] = fmaf(v1[kk], iv.y, bv[kk]);
        v2[kk] = fmaf(v2[kk], iv.z, bv[kk]);
        v3[kk] = fmaf(v3[kk], iv.w, bv[kk]);
        if (relu_out) {
          v0[kk]=fmaxf(v0[kk],0.f); v1[kk]=fmaxf(v1[kk],0.f);
          v2[kk]=fmaxf(v2[kk],0.f); v3[kk]=fmaxf(v3[kk],0.f);
        }
      }
      const int d0 = 4*Q, ko = 4*kc;
      *reinterpret_cast<float4*>(&S.feat[(d0+0)*HDIM + ko]) = make_float4(v0[0],v0[1],v0[2],v0[3]);
      *reinterpret_cast<float4*>(&S.feat[(d0+1)*HDIM + ko]) = make_float4(v1[0],v1[1],v1[2],v1[3]);
      *reinterpret_cast<float4*>(&S.feat[(d0+2)*HDIM + ko]) = make_float4(v2[0],v2[1],v2[2],v2[3]);
      if (d0 + 3 < NPG)
        *reinterpret_cast<float4*>(&S.feat[(d0+3)*HDIM + ko]) = make_float4(v3[0],v3[1],v3[2],v3[3]);
    }
  }
  __syncthreads();
}

__global__ void __launch_bounds__(NTHR, 1)
gat_fused_kernel(const float* __restrict__ x,
                 const float* __restrict__ edge_attr,
                 const float* W0, const float* as0, const float* ad0,
                 const float* We0, const float* ae0, const float* b0,
                 const float* W1, const float* as1, const float* ad1,
                 const float* We1, const float* ae1, const float* b1,
                 const float* W2, const float* as2, const float* ad2,
                 const float* We2, const float* ae2, const float* b2,
                 const float* linW, const float* linb,
                 float* __restrict__ out)
{
  extern __shared__ char smem_raw[];
  Smem& S = *reinterpret_cast<Smem*>(smem_raw);
  const int g    = blockIdx.x;
  const int tid  = threadIdx.x;
  const int warp = tid >> 5, lane = tid & 31;

  // ---- Init: small params ----
  if (tid < HDIM) {
    S.asv[0][tid]=as0[tid]; S.adv[0][tid]=ad0[tid]; S.bsh[0][tid]=b0[tid];
    S.asv[1][tid]=as1[tid]; S.adv[1][tid]=ad1[tid]; S.bsh[1][tid]=b1[tid];
    S.asv[2][tid]=as2[tid]; S.adv[2][tid]=ad2[tid]; S.bsh[2][tid]=b2[tid];
    S.w0[tid] = W0[tid];
  }
  if (warp < 6) {                  // cvec[l] = We_l @ ae_l
    const float* Wep = (warp < 2) ? We0 : (warp < 4) ? We1 : We2;
    const float* aep = (warp < 2) ? ae0 : (warp < 4) ? ae1 : ae2;
    const int l = warp >> 1, row = warp & 1;
    float p = __ldg(&Wep[row*HDIM + lane]) * __ldg(&aep[lane]);
#pragma unroll
    for (int o = 16; o; o >>= 1) p += __shfl_xor_sync(0xffffffffu, p, o);
    if (lane == 0) reinterpret_cast<float*>(&S.cvec[l])[row] = p;
  }
  if (warp == 6 || warp == 7) {    // layer-0 hs/hd scalars
    const float* av = (warp == 6) ? as0 : ad0;
    float p = __ldg(&W0[lane]) * __ldg(&av[lane]);
#pragma unroll
    for (int o = 16; o; o >>= 1) p += __shfl_xor_sync(0xffffffffu, p, o);
    if (lane == 0) S.l0s[warp - 6] = p;
  }
  if (tid < NPG) {
#pragma unroll
    for (int l = 0; l < 3; ++l) {
      S.Mpre[l][tid*PADJ + tid] = 0.f;             // diag (filled below)
      S.Mpre[l][tid*PADJ + NPG] = 0.f;             // pad column
    }
    S.xs[tid] = x[g*NPG + tid];
  }
  if (tid == NPG) S.hd[NPG] = 0.f;
  __syncthreads();

  // ---- Stream edge_attr once; scatter 3 pre-collapsed scalars (transposed) ----
  {
    const float c00=S.cvec[0].x, c01=S.cvec[0].y;
    const float c10=S.cvec[1].x, c11=S.cvec[1].y;
    const float c20=S.cvec[2].x, c21=S.cvec[2].y;
    const float2* eag = reinterpret_cast<const float2*>(edge_attr) + (size_t)g * EPG;
    for (int e = tid; e < EPG; e += NTHR) {
      const float2 v = eag[e];                     // coalesced
      const int j   = e / (NPG-1);
      const int dd0 = e - j*(NPG-1);
      const int d   = dd0 + (dd0 >= j);
      const int base = j*PADJ + d;
      S.Mpre[0][base] = fmaf(v.x, c00, v.y*c01);
      S.Mpre[1][base] = fmaf(v.x, c10, v.y*c11);
      S.Mpre[2][base] = fmaf(v.x, c20, v.y*c21);
    }
  }
  __syncthreads();

  // ---- Column sums -> diagonals (self-loop 'mean'), 3 layers fused ----
  {
    float* scr = reinterpret_cast<float*>(S.pbuf); // 21x112 scratch
    const int d = tid & 127, jc = tid >> 7;        // 7 chunks of 16 j
    if (d < PADJ) {
      const int j0 = jc*16;
      const int j1 = (j0 + 16 < NPG) ? j0 + 16 : NPG;
      float s0 = 0.f, s1 = 0.f, s2 = 0.f;
      for (int j = j0; j < j1; ++j) {
        const int o = j*PADJ + d;
        s0 += S.Mpre[0][o]; s1 += S.Mpre[1][o]; s2 += S.Mpre[2][o];
      }
      scr[jc*PADJ + d] = s0; scr[(7+jc)*PADJ + d] = s1; scr[(14+jc)*PADJ + d] = s2;
    }
    __syncthreads();
    if (tid < NPG) {
      const float inv_deg = 1.f / float(NPG-1);
#pragma unroll
      for (int l = 0; l < 3; ++l) {
        float s = 0.f;
#pragma unroll
        for (int k = 0; k < 7; ++k) s += scr[(l*7 + k)*PADJ + tid];
        S.Mpre[l][tid*PADJ + tid] = s * inv_deg;
      }
    }
  }
  __syncthreads();

  run_layer(S, warp, lane, tid, 0, false, W0);
  run_layer(S, warp, lane, tid, 1, true,  W1);
  run_layer(S, warp, lane, tid, 2, false, W2);

  // ---- global_add_pool + final linear + relu ----
  {
    float* pf = reinterpret_cast<float*>(S.pbuf);
    if (warp < 4) {
      float p = 0.f;
      for (int i = warp; i < NPG; i += 4) p += S.feat[i*HDIM + lane];
      pf[warp*HDIM + lane] = p;
    }
    __syncthreads();
    if (warp == 0) {
      const float p = pf[lane] + pf[HDIM+lane] + pf[2*HDIM+lane] + pf[3*HDIM+lane];
      float v = p * __ldg(&linW[lane]);
#pragma unroll
      for (int o = 16; o; o >>= 1) v += __shfl_xor_sync(0xffffffffu, v, o);
      if (lane == 0) out[g] = fmaxf(v + __ldg(&linb[0]), 0.f);
    }
  }
}

extern "C" void kernel_launch(void* const* d_in, const int* in_sizes, int n_in,
                              void* d_out, int out_size) {
  (void)in_sizes; (void)n_in; (void)out_size;
  cudaFuncSetAttribute(gat_fused_kernel,
                       cudaFuncAttributeMaxDynamicSharedMemorySize,
                       (int)sizeof(Smem));
  const float* x  = (const float*)d_in[0];
  const float* ea = (const float*)d_in[2];   // d_in[1] (edge_index) structural — unused
  gat_fused_kernel<<<BGRAPHS, NTHR, sizeof(Smem)>>>(
      x, ea,
      (const float*)d_in[3],  (const float*)d_in[4],  (const float*)d_in[5],
      (const float*)d_in[6],  (const float*)d_in[7],  (const float*)d_in[8],
      (const float*)d_in[9],  (const float*)d_in[10], (const float*)d_in[11],
      (const float*)d_in[12], (const float*)d_in[13], (const float*)d_in[14],
      (const float*)d_in[15], (const float*)d_in[16], (const float*)d_in[17],
      (const float*)d_in[18], (const float*)d_in[19], (const float*)d_in[20],
      (const float*)d_in[21], (const float*)d_in[22],
      (float*)d_out);
}

// round 11
// speedup vs baseline: 1.0010x; 1.0010x over previous
#include <cuda_runtime.h>

#define NPG   111
#define PADJ  112                 // padded M row width (28 quads)
#define HDIM  32
#define HDW   64                  // hdup row: 32 (h,h) pairs
#define EPG   (NPG*(NPG-1))       // 12210
#define NWARP 28
#define NTHR  (NWARP*32)          // 896
#define BGRAPHS 128

typedef unsigned long long ull;
#define FMA2(d,a,b,c) asm("fma.rn.f32x2 %0, %1, %2, %3;" : "=l"(d) : "l"(a), "l"(b), "l"(c))
#define ADD2(d,a,b)   asm("add.rn.f32x2 %0, %1, %2;" : "=l"(d) : "l"(a), "l"(b))
#define PACK2(d,lo,hi) asm("mov.b64 %0, {%1, %2};" : "=l"(d) : "f"(lo), "f"(hi))
#define UNPACK2(lo,hi,s) asm("mov.b64 {%0, %1}, %2;" : "=f"(lo), "=f"(hi) : "l"(s))

struct __align__(16) Smem {
  float Mpre[3][NPG*PADJ];          // 149184 B pre-collapsed ea.c_l; exp in place
  float feat[NPG*HDIM];             // 14208 B
  alignas(16) float hdup[NPG*HDW];  // 28416 B h duplicated (h,h), plain pair layout
  alignas(16) ull   pbuf[1792];     // 14336 B Phase-B half-1 partials (f32x2)
  alignas(16) float part[22][PADJ]; // Phase-A partials / init col-sums / pool
  alignas(16) float invbuf[PADJ];
  alignas(16) float hs[PADJ];
  float hd[PADJ];                   // hd[111]=0 pad
  float xs[PADJ];
  float asv[3][HDIM], adv[3][HDIM], bsh[3][HDIM];
  float w0[HDIM];
  float2 cvec[3];
  float l0s[2];
};

__device__ __forceinline__ void run_layer(Smem& S, int warp, int lane, int tid,
                                          int layer, bool relu_out,
                                          const float* __restrict__ Wg)
{
  // ---- (a) h = feat @ W -> hdup (h,h) pairs; fused hs/hd butterfly ----
  if (layer == 0) {                // rank-1 (input dim 1)
    const float wl = S.w0[lane], ds = S.l0s[0], dd = S.l0s[1];
    for (int i = warp; i < NPG; i += NWARP) {
      const float xv = S.xs[i];
      const float hv = xv * wl;
      ull hp; PACK2(hp, hv, hv);
      *reinterpret_cast<ull*>(&S.hdup[i*HDW + 2*lane]) = hp;
      if (lane == 0) { S.hs[i] = xv*ds; S.hd[i] = xv*dd; }
    }
  } else {
    ull wp[16];                    // W[:,lane] packed consecutive-k pairs (L2)
#pragma unroll
    for (int m2 = 0; m2 < 16; ++m2)
      PACK2(wp[m2], __ldg(&Wg[(2*m2)*HDIM + lane]), __ldg(&Wg[(2*m2+1)*HDIM + lane]));
    const float av = S.asv[layer][lane], dv = S.adv[layer][lane];
    for (int i = warp; i < NPG; i += NWARP) {
      const ulonglong2* f2 = reinterpret_cast<const ulonglong2*>(S.feat + i*HDIM);
      ull ae = 0ull, ao = 0ull;
#pragma unroll
      for (int m4 = 0; m4 < 8; ++m4) {
        const ulonglong2 f = f2[m4];           // LDS.128 broadcast
        FMA2(ae, f.x, wp[2*m4],   ae);
        FMA2(ao, f.y, wp[2*m4+1], ao);
      }
      float l0,h0,l1,h1; UNPACK2(l0,h0,ae); UNPACK2(l1,h1,ao);
      const float hv = (l0+l1) + (h0+h1);
      ull hp; PACK2(hp, hv, hv);
      *reinterpret_cast<ull*>(&S.hdup[i*HDW + 2*lane]) = hp;
      float rs = hv*av, rd = hv*dv;
#pragma unroll
      for (int o = 16; o; o >>= 1) {
        rs += __shfl_xor_sync(0xffffffffu, rs, o);
        rd += __shfl_xor_sync(0xffffffffu, rd, o);
      }
      if (lane == 0) { S.hs[i] = rs; S.hd[i] = rd; }
    }
  }
  __syncthreads();

  // ---- (b) Phase A: alpha -> exp in place; 14 partial rows ----
  {
    float* M = S.Mpre[layer];
    const int dp = tid & 63, jc = tid >> 6;        // jc in [0,14)
    if (dp < 56) {
      const int d0 = 2*dp;
      const float hd0 = S.hd[d0], hd1 = S.hd[d0+1];
      const int j0 = jc*8;
      const int j1 = (j0 + 8 < NPG) ? j0 + 8 : NPG;
      float s0 = 0.f, s1 = 0.f;
#pragma unroll 2
      for (int j = j0; j < j1; ++j) {
        const float2 m = *reinterpret_cast<const float2*>(&M[j*PADJ + d0]);
        const float hsj = S.hs[j];                 // broadcast
        float a0 = m.x + hsj + hd0;
        float a1 = m.y + hsj + hd1;
        a0 = fmaxf(a0, 0.2f*a0);                   // leaky_relu
        a1 = fmaxf(a1, 0.2f*a1);
        const float e0 = __expf(a0), e1 = __expf(a1);
        *reinterpret_cast<float2*>(&M[j*PADJ + d0]) = make_float2(e0, e1);
        s0 += e0; s1 += e1;
      }
      *reinterpret_cast<float2*>(&S.part[jc][d0]) = make_float2(s0, s1);
    }
  }
  __syncthreads();

  // ---- (c) Phase B: 14 groups x 8 dsts x 2 j-halves; f32x2 FMA, no PACK ----
  {
    const int half = warp / 14, wgrp = warp % 14;
    const ulonglong2* Mv = reinterpret_cast<const ulonglong2*>(S.Mpre[layer]);
    const int q0 = 2*wgrp, q1 = q0 + 1;
    if (half == 1 && lane < 8) {                   // inv softmax sums -> SMEM
      const int d = 8*wgrp + lane;
      float s = 0.f;
#pragma unroll
      for (int k = 0; k < 14; ++k) s += S.part[k][d];
      S.invbuf[d] = 1.f / s;
    }
    const int j0 = half ? 56 : 0, j1 = half ? NPG : 56;
    ull A0=0ull, A1=0ull, A2=0ull, A3=0ull;        // dst pairs (8w..8w+7)
#pragma unroll 4
    for (int j = j0; j < j1; ++j) {
      const ulonglong2 Pa = Mv[j*28 + q0];         // LDS.128 broadcast
      const ulonglong2 Pb = Mv[j*28 + q1];
      const ull h2 = *reinterpret_cast<const ull*>(&S.hdup[j*HDW + 2*lane]);
      FMA2(A0, Pa.x, h2, A0);
      FMA2(A1, Pa.y, h2, A1);
      FMA2(A2, Pb.x, h2, A2);
      FMA2(A3, Pb.y, h2, A3);
    }
    const int pbase = (wgrp*4)*32 + lane;          // ull slots, stride 32/pair
    if (half == 1) {                               // dump partials (4 STS.64)
      S.pbuf[pbase+0]  = A0; S.pbuf[pbase+32] = A1;
      S.pbuf[pbase+64] = A2; S.pbuf[pbase+96] = A3;
    }
    __syncthreads();
    if (half == 0) {                               // combine + scale + store
      ull t;
      t = S.pbuf[pbase+0];  ADD2(A0, A0, t);
      t = S.pbuf[pbase+32]; ADD2(A1, A1, t);
      t = S.pbuf[pbase+64]; ADD2(A2, A2, t);
      t = S.pbuf[pbase+96]; ADD2(A3, A3, t);
      float r[8];
      UNPACK2(r[0], r[1], A0); UNPACK2(r[2], r[3], A1);
      UNPACK2(r[4], r[5], A2); UNPACK2(r[6], r[7], A3);
      const float bk = S.bsh[layer][lane];
#pragma unroll
      for (int s = 0; s < 8; ++s) {
        const int d = 8*wgrp + s;
        if (d < NPG) {
          float v = fmaf(r[s], S.invbuf[d], bk);
          if (relu_out) v = fmaxf(v, 0.f);
          S.feat[d*HDIM + lane] = v;
        }
      }
    }
  }
  __syncthreads();
}

__global__ void __launch_bounds__(NTHR, 1)
gat_fused_kernel(const float* __restrict__ x,
                 const float* __restrict__ edge_attr,
                 const float* W0, const float* as0, const float* ad0,
                 const float* We0, const float* ae0, const float* b0,
                 const float* W1, const float* as1, const float* ad1,
                 const float* We1, const float* ae1, const float* b1,
                 const float* W2, const float* as2, const float* ad2,
                 const float* We2, const float* ae2, const float* b2,
                 const float* linW, const float* linb,
                 float* __restrict__ out)
{
  extern __shared__ char smem_raw[];
  Smem& S = *reinterpret_cast<Smem*>(smem_raw);
  const int g    = blockIdx.x;
  const int tid  = threadIdx.x;
  const int warp = tid >> 5, lane = tid & 31;

  // ---- Init: small params ----
  if (tid < HDIM) {
    S.asv[0][tid]=as0[tid]; S.adv[0][tid]=ad0[tid]; S.bsh[0][tid]=b0[tid];
    S.asv[1][tid]=as1[tid]; S.adv[1][tid]=ad1[tid]; S.bsh[1][tid]=b1[tid];
    S.asv[2][tid]=as2[tid]; S.adv[2][tid]=ad2[tid]; S.bsh[2][tid]=b2[tid];
    S.w0[tid] = W0[tid];
  }
  if (warp < 6) {                  // cvec[l] = We_l @ ae_l
    const float* Wep = (warp < 2) ? We0 : (warp < 4) ? We1 : We2;
    const float* aep = (warp < 2) ? ae0 : (warp < 4) ? ae1 : ae2;
    const int l = warp >> 1, row = warp & 1;
    float p = __ldg(&Wep[row*HDIM + lane]) * __ldg(&aep[lane]);
#pragma unroll
    for (int o = 16; o; o >>= 1) p += __shfl_xor_sync(0xffffffffu, p, o);
    if (lane == 0) reinterpret_cast<float*>(&S.cvec[l])[row] = p;
  }
  if (warp == 6 || warp == 7) {    // layer-0 hs/hd scalars
    const float* av = (warp == 6) ? as0 : ad0;
    float p = __ldg(&W0[lane]) * __ldg(&av[lane]);
#pragma unroll
    for (int o = 16; o; o >>= 1) p += __shfl_xor_sync(0xffffffffu, p, o);
    if (lane == 0) S.l0s[warp - 6] = p;
  }
  if (tid < NPG) {
#pragma unroll
    for (int l = 0; l < 3; ++l) {
      S.Mpre[l][tid*PADJ + tid] = 0.f;             // diag (filled below)
      S.Mpre[l][tid*PADJ + NPG] = 0.f;             // pad column
    }
    S.xs[tid] = x[g*NPG + tid];
  }
  if (tid == NPG) S.hd[NPG] = 0.f;
  __syncthreads();

  // ---- Stream edge_attr once; scatter 3 pre-collapsed scalars (transposed) ----
  {
    const float c00=S.cvec[0].x, c01=S.cvec[0].y;
    const float c10=S.cvec[1].x, c11=S.cvec[1].y;
    const float c20=S.cvec[2].x, c21=S.cvec[2].y;
    const float2* eag = reinterpret_cast<const float2*>(edge_attr) + (size_t)g * EPG;
    for (int e = tid; e < EPG; e += NTHR) {
      const float2 v = eag[e];                     // coalesced
      const int j   = e / (NPG-1);
      const int dd0 = e - j*(NPG-1);
      const int d   = dd0 + (dd0 >= j);
      const int base = j*PADJ + d;
      S.Mpre[0][base] = fmaf(v.x, c00, v.y*c01);
      S.Mpre[1][base] = fmaf(v.x, c10, v.y*c11);
      S.Mpre[2][base] = fmaf(v.x, c20, v.y*c21);
    }
  }
  __syncthreads();

  // ---- Column sums -> diagonals (self-loop 'mean'), 3 layers fused ----
  {
    const int d = tid & 127, jc = tid >> 7;        // 7 chunks of 16 j
    if (d < PADJ) {
      const int j0 = jc*16;
      const int j1 = (j0 + 16 < NPG) ? j0 + 16 : NPG;
      float s0 = 0.f, s1 = 0.f, s2 = 0.f;
      for (int j = j0; j < j1; ++j) {
        const int o = j*PADJ + d;
        s0 += S.Mpre[0][o]; s1 += S.Mpre[1][o]; s2 += S.Mpre[2][o];
      }
      S.part[jc][d] = s0; S.part[7+jc][d] = s1; S.part[14+jc][d] = s2;
    }
    __syncthreads();
    if (tid < NPG) {
      const float inv_deg = 1.f / float(NPG-1);
#pragma unroll
      for (int l = 0; l < 3; ++l) {
        float s = 0.f;
#pragma unroll
        for (int k = 0; k < 7; ++k) s += S.part[l*7 + k][tid];
        S.Mpre[l][tid*PADJ + tid] = s * inv_deg;
      }
    }
  }
  __syncthreads();

  run_layer(S, warp, lane, tid, 0, false, W0);
  run_layer(S, warp, lane, tid, 1, true,  W1);
  run_layer(S, warp, lane, tid, 2, false, W2);

  // ---- global_add_pool + final linear + relu ----
  if (warp < 4) {
    float p = 0.f;
    for (int i = warp; i < NPG; i += 4) p += S.feat[i*HDIM + lane];
    S.part[warp][lane] = p;
  }
  __syncthreads();
  if (warp == 0) {
    const float p = S.part[0][lane] + S.part[1][lane] +
                    S.part[2][lane] + S.part[3][lane];
    float v = p * __ldg(&linW[lane]);
#pragma unroll
    for (int o = 16; o; o >>= 1) v += __shfl_xor_sync(0xffffffffu, v, o);
    if (lane == 0) out[g] = fmaxf(v + __ldg(&linb[0]), 0.f);
  }
}

extern "C" void kernel_launch(void* const* d_in, const int* in_sizes, int n_in,
                              void* d_out, int out_size) {
  (void)in_sizes; (void)n_in; (void)out_size;
  cudaFuncSetAttribute(gat_fused_kernel,
                       cudaFuncAttributeMaxDynamicSharedMemorySize,
                       (int)sizeof(Smem));
  const float* x  = (const float*)d_in[0];
  const float* ea = (const float*)d_in[2];   // d_in[1] (edge_index) structural — unused
  gat_fused_kernel<<<BGRAPHS, NTHR, sizeof(Smem)>>>(
      x, ea,
      (const float*)d_in[3],  (const float*)d_in[4],  (const float*)d_in[5],
      (const float*)d_in[6],  (const float*)d_in[7],  (const float*)d_in[8],
      (const float*)d_in[9],  (const float*)d_in[10], (const float*)d_in[11],
      (const float*)d_in[12], (const float*)d_in[13], (const float*)d_in[14],
      (const float*)d_in[15], (const float*)d_in[16], (const float*)d_in[17],
      (const float*)d_in[18], (const float*)d_in[19], (const float*)d_in[20],
      (const float*)d_in[21], (const float*)d_in[22],
      (float*)d_out);
}

// round 12
// speedup vs baseline: 1.1504x; 1.1493x over previous
#include <cuda_runtime.h>

#define NPG   111
#define PADJ  112                 // padded M row width (28 quads)
#define HS    33                  // h row stride (conflict-free)
#define HDIM  32
#define EPG   (NPG*(NPG-1))       // 12210
#define NWARP 28
#define NTHR  (NWARP*32)          // 896
#define BGRAPHS 128

typedef unsigned long long ull;
#define FMA2(d,a,b,c) asm("fma.rn.f32x2 %0, %1, %2, %3;" : "=l"(d) : "l"(a), "l"(b), "l"(c))
#define ADD2(d,a,b)   asm("add.rn.f32x2 %0, %1, %2;" : "=l"(d) : "l"(a), "l"(b))
#define PACK2(d,lo,hi) asm("mov.b64 %0, {%1, %2};" : "=l"(d) : "f"(lo), "f"(hi))
#define UNPACK2(lo,hi,s) asm("mov.b64 {%0, %1}, %2;" : "=f"(lo), "=f"(hi) : "l"(s))

struct __align__(16) Smem {
  float Mpre[3][NPG*PADJ];          // 149184 B pre-collapsed ea.c_l; exp in place
  float feat[NPG*HDIM];             // 14208 B
  alignas(16) float h[NPG*HS+3];    // h = feat @ W (stride 33)
  alignas(16) ull   pbuf[1792];     // 14336 B Phase-B half-1 partials (f32x2)
  alignas(16) float part[22][PADJ]; // Phase-A partials / init col-sums / pool
  alignas(16) float invbuf[PADJ];
  alignas(16) float hs[PADJ];
  alignas(16) float hd[PADJ];       // hd[111]=0 pad
  alignas(16) float xs[PADJ];
  alignas(16) float asv[3][HDIM];
  alignas(16) float adv[3][HDIM];
  alignas(16) float bsh[3][HDIM];
  float w0[HDIM];
  float2 cvec[3];
  float l0s[2];
};

__device__ __forceinline__ void run_layer(Smem& S, int warp, int lane, int tid,
                                          int layer, bool relu_out,
                                          const float* __restrict__ Wg)
{
  // ---- (a) h = feat @ W (stride-33 store); hs/hd via in-warp readback ----
  if (layer == 0) {                // rank-1 (input dim 1)
    const float wl = S.w0[lane], ds = S.l0s[0], dd = S.l0s[1];
    for (int i = warp; i < NPG; i += NWARP) {
      const float xv = S.xs[i];
      S.h[i*HS + lane] = xv * wl;
      if (lane == 0) { S.hs[i] = xv*ds; S.hd[i] = xv*dd; }
    }
  } else {
    ull wp[16];                    // W[:,lane] packed consecutive-k pairs (L2)
#pragma unroll
    for (int m2 = 0; m2 < 16; ++m2)
      PACK2(wp[m2], __ldg(&Wg[(2*m2)*HDIM + lane]), __ldg(&Wg[(2*m2+1)*HDIM + lane]));
    for (int i = warp; i < NPG; i += NWARP) {
      const ulonglong2* f2 = reinterpret_cast<const ulonglong2*>(S.feat + i*HDIM);
      ull ae = 0ull, ao = 0ull;
#pragma unroll
      for (int m4 = 0; m4 < 8; ++m4) {
        const ulonglong2 f = f2[m4];           // LDS.128 broadcast
        FMA2(ae, f.x, wp[2*m4],   ae);
        FMA2(ao, f.y, wp[2*m4+1], ao);
      }
      float l0,h0,l1,h1; UNPACK2(l0,h0,ae); UNPACK2(l1,h1,ao);
      S.h[i*HS + lane] = (l0+l1) + (h0+h1);
    }
    __syncwarp();                  // warp reads back only ITS OWN rows
    {
      const int t = lane >> 3, kc = lane & 7;  // row-slot t, k-chunk kc (4 k's)
      const int row  = warp + 28*t;            // same rows as the loop above
      const int rowc = (row < NPG) ? row : NPG-1;
      const float* hr = &S.h[rowc*HS + 4*kc];  // odd stride -> bank-spread
      const float h0 = hr[0], h1 = hr[1], h2 = hr[2], h3 = hr[3];
      const float4 a4 = *reinterpret_cast<const float4*>(&S.asv[layer][4*kc]);
      const float4 d4 = *reinterpret_cast<const float4*>(&S.adv[layer][4*kc]);
      float ss = fmaf(h0,a4.x, fmaf(h1,a4.y, fmaf(h2,a4.z, h3*a4.w)));
      float sd = fmaf(h0,d4.x, fmaf(h1,d4.y, fmaf(h2,d4.z, h3*d4.w)));
#pragma unroll
      for (int o = 4; o; o >>= 1) {            // reduce over kc (3 shfl)
        ss += __shfl_xor_sync(0xffffffffu, ss, o);
        sd += __shfl_xor_sync(0xffffffffu, sd, o);
      }
      if (kc == 0 && row < NPG) { S.hs[row] = ss; S.hd[row] = sd; }
    }
  }
  __syncthreads();

  // ---- (b) Phase A: alpha -> exp in place; hs hoisted to float4 ----
  {
    float* M = S.Mpre[layer];
    const int dp = tid & 63, jc = tid >> 6;    // jc in [0,14)
    if (dp < 56) {
      const int d0 = 2*dp;
      const float hd0 = S.hd[d0], hd1 = S.hd[d0+1];
      const int j0 = jc*8;
      const float4 hsa = *reinterpret_cast<const float4*>(&S.hs[j0]);
      const float4 hsb = *reinterpret_cast<const float4*>(&S.hs[j0+4]);
      const float hsv[8] = {hsa.x,hsa.y,hsa.z,hsa.w, hsb.x,hsb.y,hsb.z,hsb.w};
      const int nj = (j0 + 8 <= NPG) ? 8 : NPG - j0;   // jc=13 -> 7
      float s0 = 0.f, s1 = 0.f;
#pragma unroll
      for (int jj = 0; jj < 8; ++jj) {
        if (jj < nj) {
          const int j = j0 + jj;
          const float2 m = *reinterpret_cast<const float2*>(&M[j*PADJ + d0]);
          float a0 = m.x + hsv[jj] + hd0;
          float a1 = m.y + hsv[jj] + hd1;
          a0 = fmaxf(a0, 0.2f*a0);             // leaky_relu
          a1 = fmaxf(a1, 0.2f*a1);
          const float e0 = __expf(a0), e1 = __expf(a1);
          *reinterpret_cast<float2*>(&M[j*PADJ + d0]) = make_float2(e0, e1);
          s0 += e0; s1 += e1;
        }
      }
      *reinterpret_cast<float2*>(&S.part[jc][d0]) = make_float2(s0, s1);
    }
  }
  __syncthreads();

  // ---- (c) Phase B: 14 groups x 8 dsts x 2 j-halves; f32x2 combine ----
  {
    const int half = warp / 14, wgrp = warp % 14;
    const ulonglong2* Mv = reinterpret_cast<const ulonglong2*>(S.Mpre[layer]);
    const int q0 = 2*wgrp, q1 = q0 + 1;
    if (half == 1 && lane < 8) {               // inv softmax sums -> SMEM
      const int d = 8*wgrp + lane;
      float s = 0.f;
#pragma unroll
      for (int k = 0; k < 14; ++k) s += S.part[k][d];
      S.invbuf[d] = 1.f / s;
    }
    const int j0 = half ? 56 : 0, j1 = half ? NPG : 56;
    ull A0=0ull, A1=0ull, A2=0ull, A3=0ull;    // dst pairs 8w..8w+7
#pragma unroll 4
    for (int j = j0; j < j1; ++j) {
      const ulonglong2 Pa = Mv[j*28 + q0];     // LDS.128 broadcast
      const ulonglong2 Pb = Mv[j*28 + q1];
      const float hv = S.h[j*HS + lane];       // 128B distinct: 1 wf
      ull hv2; PACK2(hv2, hv, hv);
      FMA2(A0, Pa.x, hv2, A0);
      FMA2(A1, Pa.y, hv2, A1);
      FMA2(A2, Pb.x, hv2, A2);
      FMA2(A3, Pb.y, hv2, A3);
    }
    const int pbase = wgrp*128 + lane;         // ull slots
    if (half == 1) {                           // dump partials (4 STS.64)
      S.pbuf[pbase+0]  = A0; S.pbuf[pbase+32] = A1;
      S.pbuf[pbase+64] = A2; S.pbuf[pbase+96] = A3;
    }
    __syncthreads();
    if (half == 0) {                           // combine + scale + store
      ull t;
      t = S.pbuf[pbase+0];  ADD2(A0, A0, t);
      t = S.pbuf[pbase+32]; ADD2(A1, A1, t);
      t = S.pbuf[pbase+64]; ADD2(A2, A2, t);
      t = S.pbuf[pbase+96]; ADD2(A3, A3, t);
      float r[8];
      UNPACK2(r[0], r[1], A0); UNPACK2(r[2], r[3], A1);
      UNPACK2(r[4], r[5], A2); UNPACK2(r[6], r[7], A3);
      const float bk = S.bsh[layer][lane];
#pragma unroll
      for (int s = 0; s < 8; ++s) {
        const int d = 8*wgrp + s;
        if (d < NPG) {
          float v = fmaf(r[s], S.invbuf[d], bk);
          if (relu_out) v = fmaxf(v, 0.f);
          S.feat[d*HDIM + lane] = v;
        }
      }
    }
  }
  __syncthreads();
}

__global__ void __launch_bounds__(NTHR, 1)
gat_fused_kernel(const float* __restrict__ x,
                 const float* __restrict__ edge_attr,
                 const float* W0, const float* as0, const float* ad0,
                 const float* We0, const float* ae0, const float* b0,
                 const float* W1, const float* as1, const float* ad1,
                 const float* We1, const float* ae1, const float* b1,
                 const float* W2, const float* as2, const float* ad2,
                 const float* We2, const float* ae2, const float* b2,
                 const float* linW, const float* linb,
                 float* __restrict__ out)
{
  extern __shared__ char smem_raw[];
  Smem& S = *reinterpret_cast<Smem*>(smem_raw);
  const int g    = blockIdx.x;
  const int tid  = threadIdx.x;
  const int warp = tid >> 5, lane = tid & 31;

  // ---- Init: small params ----
  if (tid < HDIM) {
    S.asv[0][tid]=as0[tid]; S.adv[0][tid]=ad0[tid]; S.bsh[0][tid]=b0[tid];
    S.asv[1][tid]=as1[tid]; S.adv[1][tid]=ad1[tid]; S.bsh[1][tid]=b1[tid];
    S.asv[2][tid]=as2[tid]; S.adv[2][tid]=ad2[tid]; S.bsh[2][tid]=b2[tid];
    S.w0[tid] = W0[tid];
  }
  if (warp < 6) {                  // cvec[l] = We_l @ ae_l
    const float* Wep = (warp < 2) ? We0 : (warp < 4) ? We1 : We2;
    const float* aep = (warp < 2) ? ae0 : (warp < 4) ? ae1 : ae2;
    const int l = warp >> 1, row = warp & 1;
    float p = __ldg(&Wep[row*HDIM + lane]) * __ldg(&aep[lane]);
#pragma unroll
    for (int o = 16; o; o >>= 1) p += __shfl_xor_sync(0xffffffffu, p, o);
    if (lane == 0) reinterpret_cast<float*>(&S.cvec[l])[row] = p;
  }
  if (warp == 6 || warp == 7) {    // layer-0 hs/hd scalars
    const float* av = (warp == 6) ? as0 : ad0;
    float p = __ldg(&W0[lane]) * __ldg(&av[lane]);
#pragma unroll
    for (int o = 16; o; o >>= 1) p += __shfl_xor_sync(0xffffffffu, p, o);
    if (lane == 0) S.l0s[warp - 6] = p;
  }
  if (tid < NPG) {
#pragma unroll
    for (int l = 0; l < 3; ++l) {
      S.Mpre[l][tid*PADJ + tid] = 0.f;             // diag (filled below)
      S.Mpre[l][tid*PADJ + NPG] = 0.f;             // pad column
    }
    S.xs[tid] = x[g*NPG + tid];
  }
  if (tid == NPG) S.hd[NPG] = 0.f;
  __syncthreads();

  // ---- Stream edge_attr once; scatter 3 pre-collapsed scalars (transposed) ----
  {
    const float c00=S.cvec[0].x, c01=S.cvec[0].y;
    const float c10=S.cvec[1].x, c11=S.cvec[1].y;
    const float c20=S.cvec[2].x, c21=S.cvec[2].y;
    const float2* eag = reinterpret_cast<const float2*>(edge_attr) + (size_t)g * EPG;
    for (int e = tid; e < EPG; e += NTHR) {
      const float2 v = eag[e];                     // coalesced
      const int j   = e / (NPG-1);
      const int dd0 = e - j*(NPG-1);
      const int d   = dd0 + (dd0 >= j);
      const int base = j*PADJ + d;
      S.Mpre[0][base] = fmaf(v.x, c00, v.y*c01);
      S.Mpre[1][base] = fmaf(v.x, c10, v.y*c11);
      S.Mpre[2][base] = fmaf(v.x, c20, v.y*c21);
    }
  }
  __syncthreads();

  // ---- Column sums -> diagonals (self-loop 'mean'), 3 layers fused ----
  {
    const int d = tid & 127, jc = tid >> 7;        // 7 chunks of 16 j
    if (d < PADJ) {
      const int j0 = jc*16;
      const int j1 = (j0 + 16 < NPG) ? j0 + 16 : NPG;
      float s0 = 0.f, s1 = 0.f, s2 = 0.f;
      for (int j = j0; j < j1; ++j) {
        const int o = j*PADJ + d;
        s0 += S.Mpre[0][o]; s1 += S.Mpre[1][o]; s2 += S.Mpre[2][o];
      }
      S.part[jc][d] = s0; S.part[7+jc][d] = s1; S.part[14+jc][d] = s2;
    }
    __syncthreads();
    if (tid < NPG) {
      const float inv_deg = 1.f / float(NPG-1);
#pragma unroll
      for (int l = 0; l < 3; ++l) {
        float s = 0.f;
#pragma unroll
        for (int k = 0; k < 7; ++k) s += S.part[l*7 + k][tid];
        S.Mpre[l][tid*PADJ + tid] = s * inv_deg;
      }
    }
  }
  __syncthreads();

  run_layer(S, warp, lane, tid, 0, false, W0);
  run_layer(S, warp, lane, tid, 1, true,  W1);
  run_layer(S, warp, lane, tid, 2, false, W2);

  // ---- global_add_pool + final linear + relu ----
  if (warp < 4) {
    float p = 0.f;
    for (int i = warp; i < NPG; i += 4) p += S.feat[i*HDIM + lane];
    S.part[warp][lane] = p;
  }
  __syncthreads();
  if (warp == 0) {
    const float p = S.part[0][lane] + S.part[1][lane] +
                    S.part[2][lane] + S.part[3][lane];
    float v = p * __ldg(&linW[lane]);
#pragma unroll
    for (int o = 16; o; o >>= 1) v += __shfl_xor_sync(0xffffffffu, v, o);
    if (lane == 0) out[g] = fmaxf(v + __ldg(&linb[0]), 0.f);
  }
}

extern "C" void kernel_launch(void* const* d_in, const int* in_sizes, int n_in,
                              void* d_out, int out_size) {
  (void)in_sizes; (void)n_in; (void)out_size;
  cudaFuncSetAttribute(gat_fused_kernel,
                       cudaFuncAttributeMaxDynamicSharedMemorySize,
                       (int)sizeof(Smem));
  const float* x  = (const float*)d_in[0];
  const float* ea = (const float*)d_in[2];   // d_in[1] (edge_index) structural — unused
  gat_fused_kernel<<<BGRAPHS, NTHR, sizeof(Smem)>>>(
      x, ea,
      (const float*)d_in[3],  (const float*)d_in[4],  (const float*)d_in[5],
      (const float*)d_in[6],  (const float*)d_in[7],  (const float*)d_in[8],
      (const float*)d_in[9],  (const float*)d_in[10], (const float*)d_in[11],
      (const float*)d_in[12], (const float*)d_in[13], (const float*)d_in[14],
      (const float*)d_in[15], (const float*)d_in[16], (const float*)d_in[17],
      (const float*)d_in[18], (const float*)d_in[19], (const float*)d_in[20],
      (const float*)d_in[21], (const float*)d_in[22],
      (float*)d_out);
}